// round 2
// baseline (speedup 1.0000x reference)
#include <cuda_runtime.h>
#include <cuda_bf16.h>
#include <cstdint>

#define F_SPARSE 26
#define BATCH    4096
#define EMB      128   // D
#define ATT      64    // A
#define BT       4     // batch rows per CTA
#define ROWS     (F_SPARSE * BT)   // 104
#define RPAD     112               // padded to 7 * 16
#define NPAIR    325
#define NTHREADS 256

// SMEM layout (bytes). A/B tiles in bf16 with 8-elem row pad for ldmatrix
// bank-conflict avoidance (row pitch 272B -> bank shift 4/row).
#define KPITCH   136               // bf16 elems per row
#define ROWB     (KPITCH * 2)      // 272 bytes
#define SA_HI    0
#define SA_SZ    (RPAD * ROWB)     // 30464
#define SA_LO    (SA_HI + SA_SZ)   // 30464
#define SB_HI    (SA_LO + SA_SZ)   // 60928
#define SB_SZ    (128 * ROWB)      // 34816
#define SB_LO    (SB_HI + SB_SZ)   // 95744
#define SOUT_OFF (SB_LO + SB_SZ)   // 130560
#define SOUT_PITCH 328
#define SMEM_TOTAL (SOUT_OFF + BT * SOUT_PITCH * 4)  // 135808
// sX (fp32, 104 x 132) aliases the sA region after MMA: 54912 <= 60928
#define XPITCH   132

__device__ __forceinline__ uint32_t cvta_s(const void* p) {
    return (uint32_t)__cvta_generic_to_shared(p);
}

__device__ __forceinline__ void ldsm_x4(uint32_t a[4], uint32_t addr) {
    asm volatile("ldmatrix.sync.aligned.m8n8.x4.shared.b16 {%0,%1,%2,%3}, [%4];"
                 : "=r"(a[0]), "=r"(a[1]), "=r"(a[2]), "=r"(a[3]) : "r"(addr));
}
__device__ __forceinline__ void ldsm_x2(uint32_t b[2], uint32_t addr) {
    asm volatile("ldmatrix.sync.aligned.m8n8.x2.shared.b16 {%0,%1}, [%2];"
                 : "=r"(b[0]), "=r"(b[1]) : "r"(addr));
}
__device__ __forceinline__ void mma_bf16(float c[4], const uint32_t a[4], const uint32_t b[2]) {
    asm volatile("mma.sync.aligned.m16n8k16.row.col.f32.bf16.bf16.f32 "
                 "{%0,%1,%2,%3}, {%4,%5,%6,%7}, {%8,%9}, {%0,%1,%2,%3};"
                 : "+f"(c[0]), "+f"(c[1]), "+f"(c[2]), "+f"(c[3])
                 : "r"(a[0]), "r"(a[1]), "r"(a[2]), "r"(a[3]), "r"(b[0]), "r"(b[1]));
}

__global__ void __launch_bounds__(NTHREADS, 1)
attn_inter_kernel(const float* __restrict__ emb, const float* __restrict__ W1,
                  const float* __restrict__ b1,  const float* __restrict__ W2,
                  const float* __restrict__ b2,  float* __restrict__ out)
{
    extern __shared__ char smem[];
    const int tid   = threadIdx.x;
    const int lane  = tid & 31;
    const int warp  = tid >> 5;
    const int bbase = blockIdx.x * BT;

    // ---------------- Fill A tile: embeddings -> bf16 hi/lo split -----------
    // row r = f*BT + b_local, k contiguous. Coalesced float4 global reads.
    for (int idx = tid; idx < RPAD * 32; idx += NTHREADS) {
        const int r  = idx >> 5;
        const int kq = idx & 31;          // k = 4*kq
        float4 v;
        if (r < ROWS) {
            const int f  = r >> 2;
            const int bl = r & 3;
            v = reinterpret_cast<const float4*>(emb)[(f * BATCH + bbase + bl) * 32 + kq];
        } else {
            v = make_float4(0.f, 0.f, 0.f, 0.f);
        }
        float vv[4] = {v.x, v.y, v.z, v.w};
        __nv_bfloat16 h[4], l[4];
        #pragma unroll
        for (int t = 0; t < 4; ++t) {
            h[t] = __float2bfloat16(vv[t]);
            l[t] = __float2bfloat16(vv[t] - __bfloat162float(h[t]));
        }
        char* pH = smem + SA_HI + r * ROWB + kq * 8;
        char* pL = smem + SA_LO + r * ROWB + kq * 8;
        __nv_bfloat162 h01; h01.x = h[0]; h01.y = h[1];
        __nv_bfloat162 h23; h23.x = h[2]; h23.y = h[3];
        __nv_bfloat162 l01; l01.x = l[0]; l01.y = l[1];
        __nv_bfloat162 l23; l23.x = l[2]; l23.y = l[3];
        reinterpret_cast<__nv_bfloat162*>(pH)[0] = h01;
        reinterpret_cast<__nv_bfloat162*>(pH)[1] = h23;
        reinterpret_cast<__nv_bfloat162*>(pL)[0] = l01;
        reinterpret_cast<__nv_bfloat162*>(pL)[1] = l23;
    }

    // ---------------- Fill B tile: W1concat, stored [n][k] (col-major B) ----
    // W1c[k][n] = W1[k][n] (n<64, Pa) or W1[128+k][n-64] (n>=64, Pb)
    for (int idx = tid; idx < 128 * 32; idx += NTHREADS) {
        const int k  = idx >> 5;
        const int nq = idx & 31;
        const int n0 = nq * 4;            // all 4 n's on same side of 64
        const float* src = (n0 < 64) ? (W1 + k * ATT + n0)
                                     : (W1 + (EMB + k) * ATT + (n0 - 64));
        float4 v = *reinterpret_cast<const float4*>(src);
        float vv[4] = {v.x, v.y, v.z, v.w};
        #pragma unroll
        for (int t = 0; t < 4; ++t) {
            __nv_bfloat16 h = __float2bfloat16(vv[t]);
            __nv_bfloat16 l = __float2bfloat16(vv[t] - __bfloat162float(h));
            *reinterpret_cast<__nv_bfloat16*>(smem + SB_HI + (n0 + t) * ROWB + k * 2) = h;
            *reinterpret_cast<__nv_bfloat16*>(smem + SB_LO + (n0 + t) * ROWB + k * 2) = l;
        }
    }
    __syncthreads();

    // ---------------- Stage 1 MMA: X = E @ W1c via 3-pass bf16 split --------
    float acc[16][4];
    #pragma unroll
    for (int nt = 0; nt < 16; ++nt) {
        acc[nt][0] = 0.f; acc[nt][1] = 0.f; acc[nt][2] = 0.f; acc[nt][3] = 0.f;
    }

    if (warp < 7) {
        const int m0    = warp * 16;
        const int midx  = lane >> 3;                               // matrix 0..3
        const int arow  = m0 + ((midx & 1) << 3) + (lane & 7);
        const uint32_t aRowOff  = (uint32_t)(arow * ROWB + ((midx >> 1) << 4));
        const uint32_t bLaneOff = (uint32_t)((lane & 7) * ROWB + ((lane >> 3) & 1) * 16);
        const uint32_t saHi = cvta_s(smem + SA_HI);
        const uint32_t saLo = cvta_s(smem + SA_LO);
        const uint32_t sbHi = cvta_s(smem + SB_HI);
        const uint32_t sbLo = cvta_s(smem + SB_LO);

        #pragma unroll
        for (int term = 0; term < 3; ++term) {   // hi*hi, hi*lo, lo*hi
            const uint32_t aBase = (term == 2) ? saLo : saHi;
            const uint32_t bBase = (term == 1) ? sbLo : sbHi;
            #pragma unroll
            for (int ks = 0; ks < 8; ++ks) {
                uint32_t a[4];
                ldsm_x4(a, aBase + aRowOff + ks * 32);
                #pragma unroll
                for (int nt = 0; nt < 16; ++nt) {
                    uint32_t b[2];
                    ldsm_x2(b, bBase + bLaneOff + ks * 32 + nt * (8 * ROWB));
                    mma_bf16(acc[nt], a, b);
                }
            }
        }
    }
    __syncthreads();   // all smem A/B reads done before overwriting with X

    // ---------------- Spill X to SMEM (aliases A region) --------------------
    float* sX = reinterpret_cast<float*>(smem);
    if (warp < 7) {
        const int m0   = warp * 16 + (lane >> 2);
        const int ncol = (lane & 3) * 2;
        #pragma unroll
        for (int nt = 0; nt < 16; ++nt) {
            const int n = nt * 8 + ncol;
            *reinterpret_cast<float2*>(sX + m0 * XPITCH + n) =
                make_float2(acc[nt][0], acc[nt][1]);
            const int m1 = m0 + 8;
            if (m1 < ROWS)
                *reinterpret_cast<float2*>(sX + m1 * XPITCH + n) =
                    make_float2(acc[nt][2], acc[nt][3]);
        }
    }
    __syncthreads();

    // ---------------- Stage 2: pairwise relu + dot(W2) ----------------------
    // warp -> (b_local = warp&3, half = warp>>2); lane covers a = 2*lane,2*lane+1
    {
        const int bl   = warp & 3;
        const int half = warp >> 2;
        const float b1x = b1[2 * lane], b1y = b1[2 * lane + 1];
        const float w2x = W2[2 * lane], w2y = W2[2 * lane + 1];
        float* so = reinterpret_cast<float*>(smem + SOUT_OFF) + bl * SOUT_PITCH;

        #pragma unroll
        for (int i = 0; i < 25; ++i) {
            const float* rowi = sX + (i * BT + bl) * XPITCH;
            const float2 va = *reinterpret_cast<const float2*>(rowi + 2 * lane);
            const float pax = va.x + b1x;
            const float pay = va.y + b1y;
            const int pbase = i * 25 - (i * (i - 1)) / 2;  // pairs before row i
            for (int j = i + 1 + half; j < 26; j += 2) {
                const float* rowj = sX + (j * BT + bl) * XPITCH + 64;
                const float2 vb = *reinterpret_cast<const float2*>(rowj + 2 * lane);
                const float hx = fmaxf(pax + vb.x, 0.f);
                const float hy = fmaxf(pay + vb.y, 0.f);
                float v = fmaf(hy, w2y, hx * w2x);
                #pragma unroll
                for (int off = 16; off > 0; off >>= 1)
                    v += __shfl_xor_sync(0xffffffffu, v, off);
                if (lane == 0) so[pbase + (j - i - 1)] = v;
            }
        }
    }
    __syncthreads();

    // ---------------- Coalesced output write -------------------------------
    const float b2v = b2[0];
    const float* soAll = reinterpret_cast<const float*>(smem + SOUT_OFF);
    for (int idx = tid; idx < BT * NPAIR; idx += NTHREADS) {
        const int bl = idx / NPAIR;
        const int p  = idx - bl * NPAIR;
        out[(size_t)(bbase + bl) * NPAIR + p] = soAll[bl * SOUT_PITCH + p] + b2v;
    }
}

extern "C" void kernel_launch(void* const* d_in, const int* in_sizes, int n_in,
                              void* d_out, int out_size) {
    const float* emb = (const float*)d_in[0];
    const float* W1  = (const float*)d_in[1];
    const float* b1  = (const float*)d_in[2];
    const float* W2  = (const float*)d_in[3];
    const float* b2  = (const float*)d_in[4];
    float* out = (float*)d_out;
    (void)in_sizes; (void)n_in; (void)out_size;

    cudaFuncSetAttribute(attn_inter_kernel,
                         cudaFuncAttributeMaxDynamicSharedMemorySize, SMEM_TOTAL);
    attn_inter_kernel<<<BATCH / BT, NTHREADS, SMEM_TOTAL>>>(emb, W1, b1, W2, b2, out);
}

// round 5
// speedup vs baseline: 1.1623x; 1.1623x over previous
#include <cuda_runtime.h>
#include <cuda_bf16.h>
#include <cstdint>

#define F_SPARSE 26
#define BATCH    4096
#define EMB      128   // D
#define ATT      64    // A
#define BT       4     // batch rows per CTA
#define ROWS     (F_SPARSE * BT)   // 104
#define RPAD     112               // 7 * 16
#define NPAIR    325
#define NTHREADS 1024

// bf16 tiles with 8-elem row pad (pitch 272B) for conflict-free ldmatrix.
#define KPITCH   136
#define ROWB     (KPITCH * 2)      // 272 bytes
#define SA_HI    0
#define SA_SZ    (RPAD * ROWB)     // 30464
#define SA_LO    (SA_HI + SA_SZ)
#define SB_HI    (SA_LO + SA_SZ)   // 60928
#define SB_SZ    (128 * ROWB)      // 34816
#define SB_LO    (SB_HI + SB_SZ)
#define SVEC_OFF (SB_LO + SB_SZ)   // 130560 : b1 (64 f32) + W2 (64 f32)
#define SLUT_OFF (SVEC_OFF + 512)  // 131072 : 328-byte pair->i LUT
#define SMEM_TOTAL (SLUT_OFF + 328)  // 131400
// sX fp32 [bl][f][a] pitch 140 aliases the A region after MMA:
// 104*140*4 = 58240 <= 60928
#define XP       140

__device__ __forceinline__ uint32_t cvta_s(const void* p) {
    return (uint32_t)__cvta_generic_to_shared(p);
}
__device__ __forceinline__ void ldsm_x4(uint32_t a[4], uint32_t addr) {
    asm volatile("ldmatrix.sync.aligned.m8n8.x4.shared.b16 {%0,%1,%2,%3}, [%4];"
                 : "=r"(a[0]), "=r"(a[1]), "=r"(a[2]), "=r"(a[3]) : "r"(addr));
}
__device__ __forceinline__ void ldsm_x2(uint32_t b[2], uint32_t addr) {
    asm volatile("ldmatrix.sync.aligned.m8n8.x2.shared.b16 {%0,%1}, [%2];"
                 : "=r"(b[0]), "=r"(b[1]) : "r"(addr));
}
__device__ __forceinline__ void mma_bf16(float c[4], const uint32_t a[4], const uint32_t b[2]) {
    asm volatile("mma.sync.aligned.m16n8k16.row.col.f32.bf16.bf16.f32 "
                 "{%0,%1,%2,%3}, {%4,%5,%6,%7}, {%8,%9}, {%0,%1,%2,%3};"
                 : "+f"(c[0]), "+f"(c[1]), "+f"(c[2]), "+f"(c[3])
                 : "r"(a[0]), "r"(a[1]), "r"(a[2]), "r"(a[3]), "r"(b[0]), "r"(b[1]));
}

__global__ void __launch_bounds__(NTHREADS, 1)
attn_inter_kernel(const float* __restrict__ emb, const float* __restrict__ W1,
                  const float* __restrict__ b1,  const float* __restrict__ W2,
                  const float* __restrict__ b2,  float* __restrict__ out)
{
    extern __shared__ char smem[];
    const int tid   = threadIdx.x;
    const int lane  = tid & 31;
    const int warp  = tid >> 5;
    const int bbase = blockIdx.x * BT;

    // ---------------- Fill A tile: embeddings -> bf16 hi/lo split -----------
    for (int idx = tid; idx < RPAD * 32; idx += NTHREADS) {
        const int r  = idx >> 5;
        const int kq = idx & 31;          // k = 4*kq
        float4 v;
        if (r < ROWS) {
            const int f  = r >> 2;
            const int bl = r & 3;
            v = reinterpret_cast<const float4*>(emb)[(f * BATCH + bbase + bl) * 32 + kq];
        } else {
            v = make_float4(0.f, 0.f, 0.f, 0.f);
        }
        float vv[4] = {v.x, v.y, v.z, v.w};
        __nv_bfloat16 h[4], l[4];
        #pragma unroll
        for (int t = 0; t < 4; ++t) {
            h[t] = __float2bfloat16(vv[t]);
            l[t] = __float2bfloat16(vv[t] - __bfloat162float(h[t]));
        }
        char* pH = smem + SA_HI + r * ROWB + kq * 8;
        char* pL = smem + SA_LO + r * ROWB + kq * 8;
        __nv_bfloat162 h01; h01.x = h[0]; h01.y = h[1];
        __nv_bfloat162 h23; h23.x = h[2]; h23.y = h[3];
        __nv_bfloat162 l01; l01.x = l[0]; l01.y = l[1];
        __nv_bfloat162 l23; l23.x = l[2]; l23.y = l[3];
        reinterpret_cast<__nv_bfloat162*>(pH)[0] = h01;
        reinterpret_cast<__nv_bfloat162*>(pH)[1] = h23;
        reinterpret_cast<__nv_bfloat162*>(pL)[0] = l01;
        reinterpret_cast<__nv_bfloat162*>(pL)[1] = l23;
    }

    // ---------------- Fill B tile: W1concat stored [n][k] -------------------
    for (int idx = tid; idx < 128 * 32; idx += NTHREADS) {
        const int k  = idx >> 5;
        const int nq = idx & 31;
        const int n0 = nq * 4;
        const float* src = (n0 < 64) ? (W1 + k * ATT + n0)
                                     : (W1 + (EMB + k) * ATT + (n0 - 64));
        float4 v = *reinterpret_cast<const float4*>(src);
        float vv[4] = {v.x, v.y, v.z, v.w};
        #pragma unroll
        for (int t = 0; t < 4; ++t) {
            __nv_bfloat16 h = __float2bfloat16(vv[t]);
            __nv_bfloat16 l = __float2bfloat16(vv[t] - __bfloat162float(h));
            *reinterpret_cast<__nv_bfloat16*>(smem + SB_HI + (n0 + t) * ROWB + k * 2) = h;
            *reinterpret_cast<__nv_bfloat16*>(smem + SB_LO + (n0 + t) * ROWB + k * 2) = l;
        }
    }
    // b1 / W2 into smem for broadcast use in stage 2
    if (tid < 64) {
        reinterpret_cast<float*>(smem + SVEC_OFF)[tid]      = b1[tid];
        reinterpret_cast<float*>(smem + SVEC_OFF)[64 + tid] = W2[tid];
    }
    // pair -> i LUT (one byte per pair). Thread t handles pairs of row i=t.
    if (tid < F_SPARSE - 1) {
        const int i = tid;
        const int pbase = i * (F_SPARSE - 1) - (i * (i - 1)) / 2;
        const int cnt   = F_SPARSE - 1 - i;
        for (int t = 0; t < cnt; ++t)
            smem[SLUT_OFF + pbase + t] = (char)i;
    }
    const float b2v = b2[0];
    __syncthreads();

    // ---------------- Stage 1 MMA: X = E @ W1c, 3-pass bf16 split -----------
    // 28 working warps: warp = (mtile 0..6) * 4 + (N-quarter 0..3)
    float acc[4][4];
    #pragma unroll
    for (int nt = 0; nt < 4; ++nt) {
        acc[nt][0] = 0.f; acc[nt][1] = 0.f; acc[nt][2] = 0.f; acc[nt][3] = 0.f;
    }
    const int mtile = warp >> 2;
    const int ng    = warp & 3;

    if (warp < 28) {
        const int m0    = mtile * 16;
        const int midx  = lane >> 3;
        const int arow  = m0 + ((midx & 1) << 3) + (lane & 7);
        const uint32_t aRowOff  = (uint32_t)(arow * ROWB + ((midx >> 1) << 4));
        const uint32_t bLaneOff = (uint32_t)((lane & 7) * ROWB + ((lane >> 3) & 1) * 16);
        const uint32_t saHi = cvta_s(smem + SA_HI);
        const uint32_t saLo = cvta_s(smem + SA_LO);
        const uint32_t sbHi = cvta_s(smem + SB_HI);
        const uint32_t sbLo = cvta_s(smem + SB_LO);

        #pragma unroll
        for (int term = 0; term < 3; ++term) {   // hi*hi, hi*lo, lo*hi
            const uint32_t aBase = (term == 2) ? saLo : saHi;
            const uint32_t bBase = (term == 1) ? sbLo : sbHi;
            #pragma unroll
            for (int ks = 0; ks < 8; ++ks) {
                uint32_t a[4];
                ldsm_x4(a, aBase + aRowOff + ks * 32);
                #pragma unroll
                for (int nt = 0; nt < 4; ++nt) {
                    uint32_t b[2];
                    ldsm_x2(b, bBase + bLaneOff + ks * 32
                               + (ng * 4 + nt) * (8 * ROWB));
                    mma_bf16(acc[nt], a, b);
                }
            }
        }
    }
    __syncthreads();   // all A/B reads done before overwriting with X

    // ---------------- Spill X to SMEM as [bl][f][a], pitch XP ---------------
    float* sX = reinterpret_cast<float*>(smem);
    if (warp < 28) {
        const int mA = mtile * 16 + (lane >> 2);      // rows mA and mA+8
        const int nc = (lane & 3) * 2;
        #pragma unroll
        for (int nt = 0; nt < 4; ++nt) {
            const int n = (ng * 4 + nt) * 8 + nc;
            if (mA < ROWS) {
                const int r0 = (mA & 3) * F_SPARSE + (mA >> 2);
                *reinterpret_cast<float2*>(sX + r0 * XP + n) =
                    make_float2(acc[nt][0], acc[nt][1]);
            }
            const int mB = mA + 8;
            if (mB < ROWS) {
                const int r1 = (mB & 3) * F_SPARSE + (mB >> 2);
                *reinterpret_cast<float2*>(sX + r1 * XP + n) =
                    make_float2(acc[nt][2], acc[nt][3]);
            }
        }
    }
    __syncthreads();

    // ---------------- Stage 2: thread-per-output ----------------------------
    const float4* sB14 = reinterpret_cast<const float4*>(smem + SVEC_OFF);
    const float4* sW24 = sB14 + 16;

    for (int idx = tid; idx < BT * NPAIR; idx += NTHREADS) {
        const int bl = idx / NPAIR;
        const int p  = idx - bl * NPAIR;
        const int i  = (int)smem[SLUT_OFF + p];
        const int pbase = i * (F_SPARSE - 1) - (i * (i - 1)) / 2;
        const int j  = i + 1 + (p - pbase);

        const float4* Pa4 = reinterpret_cast<const float4*>(sX + (bl * F_SPARSE + i) * XP);
        const float4* Pb4 = reinterpret_cast<const float4*>(sX + (bl * F_SPARSE + j) * XP + 64);

        float a0 = 0.f, a1 = 0.f;
        #pragma unroll
        for (int t = 0; t < 16; ++t) {
            const float4 vi = Pa4[t];
            const float4 vj = Pb4[t];
            const float4 bb = sB14[t];
            const float4 ww = sW24[t];
            a0 = fmaf(fmaxf(vi.x + vj.x + bb.x, 0.f), ww.x, a0);
            a1 = fmaf(fmaxf(vi.y + vj.y + bb.y, 0.f), ww.y, a1);
            a0 = fmaf(fmaxf(vi.z + vj.z + bb.z, 0.f), ww.z, a0);
            a1 = fmaf(fmaxf(vi.w + vj.w + bb.w, 0.f), ww.w, a1);
        }
        out[(size_t)(bbase + bl) * NPAIR + p] = a0 + a1 + b2v;
    }
}

extern "C" void kernel_launch(void* const* d_in, const int* in_sizes, int n_in,
                              void* d_out, int out_size) {
    const float* emb = (const float*)d_in[0];
    const float* W1  = (const float*)d_in[1];
    const float* b1  = (const float*)d_in[2];
    const float* W2  = (const float*)d_in[3];
    const float* b2  = (const float*)d_in[4];
    float* out = (float*)d_out;
    (void)in_sizes; (void)n_in; (void)out_size;

    cudaFuncSetAttribute(attn_inter_kernel,
                         cudaFuncAttributeMaxDynamicSharedMemorySize, SMEM_TOTAL);
    attn_inter_kernel<<<BATCH / BT, NTHREADS, SMEM_TOTAL>>>(emb, W1, b1, W2, b2, out);
}

// round 6
// speedup vs baseline: 1.8650x; 1.6046x over previous
#include <cuda_runtime.h>
#include <cuda_bf16.h>
#include <cstdint>

#define F_SPARSE 26
#define BATCH    4096
#define EMB      128
#define ATT      64
#define NPAIR    325
#define M_TOTAL  (F_SPARSE * BATCH)   // 106496

// fp32 scratch: X[m][128], m = f*BATCH + b. 54.5 MB.
__device__ float g_X[(size_t)M_TOTAL * 128];

// ======================= Kernel 1: X = E @ W1c (+b1) =======================
#define K1_MT      256
#define K1_THREADS 512
#define ROWB       272              // 128 bf16 + 8 pad, bytes
#define SA_HI      0
#define SA_SZ      (K1_MT * ROWB)   // 69632
#define SA_LO      (SA_HI + SA_SZ)
#define SB_HI      (SA_LO + SA_SZ)  // 139264
#define SB_SZ      (128 * ROWB)     // 34816
#define SB_LO      (SB_HI + SB_SZ)
#define SVEC       (SB_LO + SB_SZ)  // 208896 : b1 (64 f32)
#define K1_SMEM    (SVEC + 256)     // 209152

__device__ __forceinline__ uint32_t cvta_s(const void* p) {
    return (uint32_t)__cvta_generic_to_shared(p);
}
__device__ __forceinline__ void ldsm_x4(uint32_t a[4], uint32_t addr) {
    asm volatile("ldmatrix.sync.aligned.m8n8.x4.shared.b16 {%0,%1,%2,%3}, [%4];"
                 : "=r"(a[0]), "=r"(a[1]), "=r"(a[2]), "=r"(a[3]) : "r"(addr));
}
__device__ __forceinline__ void ldsm_x2(uint32_t b[2], uint32_t addr) {
    asm volatile("ldmatrix.sync.aligned.m8n8.x2.shared.b16 {%0,%1}, [%2];"
                 : "=r"(b[0]), "=r"(b[1]) : "r"(addr));
}
__device__ __forceinline__ void mma_bf16(float c[4], const uint32_t a[4], const uint32_t b[2]) {
    asm volatile("mma.sync.aligned.m16n8k16.row.col.f32.bf16.bf16.f32 "
                 "{%0,%1,%2,%3}, {%4,%5,%6,%7}, {%8,%9}, {%0,%1,%2,%3};"
                 : "+f"(c[0]), "+f"(c[1]), "+f"(c[2]), "+f"(c[3])
                 : "r"(a[0]), "r"(a[1]), "r"(a[2]), "r"(a[3]), "r"(b[0]), "r"(b[1]));
}
__device__ __forceinline__ uint32_t pack_bf2(float x, float y) {
    __nv_bfloat162 t; t.x = __float2bfloat16(x); t.y = __float2bfloat16(y);
    return *reinterpret_cast<uint32_t*>(&t);
}

__global__ void __launch_bounds__(K1_THREADS, 1)
k1_gemm(const float* __restrict__ emb, const float* __restrict__ W1,
        const float* __restrict__ b1)
{
    extern __shared__ char smem[];
    const int tid  = threadIdx.x;
    const int lane = tid & 31;
    const int warp = tid >> 5;
    const int m0   = blockIdx.x * K1_MT;

    // ---- A tile fill: 256 contiguous rows of E -> bf16 hi/lo --------------
    for (int idx = tid; idx < K1_MT * 32; idx += K1_THREADS) {
        const int r = idx >> 5;
        const int c = idx & 31;                       // k = 4c
        const float4 v = reinterpret_cast<const float4*>(emb)[(size_t)(m0 + r) * 32 + c];
        float vv[4] = {v.x, v.y, v.z, v.w};
        float hv[4];
        uint32_t hi01, hi23, lo01, lo23;
        #pragma unroll
        for (int t = 0; t < 4; ++t)
            hv[t] = __bfloat162float(__float2bfloat16(vv[t]));
        hi01 = pack_bf2(vv[0], vv[1]);  hi23 = pack_bf2(vv[2], vv[3]);
        lo01 = pack_bf2(vv[0]-hv[0], vv[1]-hv[1]);
        lo23 = pack_bf2(vv[2]-hv[2], vv[3]-hv[3]);
        uint2 hpair = make_uint2(hi01, hi23);
        uint2 lpair = make_uint2(lo01, lo23);
        *reinterpret_cast<uint2*>(smem + SA_HI + r * ROWB + c * 8) = hpair;
        *reinterpret_cast<uint2*>(smem + SA_LO + r * ROWB + c * 8) = lpair;
    }
    // ---- B tile fill: W1c stored [n][k], n 0..127 -------------------------
    for (int idx = tid; idx < 128 * 64; idx += K1_THREADS) {
        const int n  = idx >> 6;       // smem row (0..127)
        const int q  = idx & 63;       // k-pair
        const int k  = 2 * q + ((n >= 64) ? 128 : 0);
        const int nc = n & 63;
        const float v0 = W1[(size_t)k * ATT + nc];
        const float v1 = W1[(size_t)(k + 1) * ATT + nc];
        const float h0 = __bfloat162float(__float2bfloat16(v0));
        const float h1 = __bfloat162float(__float2bfloat16(v1));
        *reinterpret_cast<uint32_t*>(smem + SB_HI + n * ROWB + q * 4) = pack_bf2(v0, v1);
        *reinterpret_cast<uint32_t*>(smem + SB_LO + n * ROWB + q * 4) = pack_bf2(v0-h0, v1-h1);
    }
    if (tid < 64)
        reinterpret_cast<float*>(smem + SVEC)[tid] = b1[tid];
    __syncthreads();

    // ---- MMA: 16 warps = 8 m32-subtiles x 2 n64-halves --------------------
    const int msub32 = warp >> 1;          // 0..7
    const int nhalf  = warp & 1;           // 0..1
    const int mW     = msub32 * 32;
    const int n0     = nhalf * 64;

    float acc[2][8][4];
    #pragma unroll
    for (int ms = 0; ms < 2; ++ms)
        #pragma unroll
        for (int nt = 0; nt < 8; ++nt) {
            acc[ms][nt][0]=0.f; acc[ms][nt][1]=0.f; acc[ms][nt][2]=0.f; acc[ms][nt][3]=0.f;
        }

    const int midx = lane >> 3;
    const uint32_t aOff = (uint32_t)((mW + ((midx & 1) << 3) + (lane & 7)) * ROWB
                                     + ((midx >> 1) << 4));
    const uint32_t bOff = (uint32_t)((n0 + (lane & 7)) * ROWB + (((lane >> 3) & 1) << 4));
    const uint32_t saHi = cvta_s(smem + SA_HI);
    const uint32_t saLo = cvta_s(smem + SA_LO);
    const uint32_t sbHi = cvta_s(smem + SB_HI);
    const uint32_t sbLo = cvta_s(smem + SB_LO);

    #pragma unroll
    for (int term = 0; term < 3; ++term) {   // hi*hi, hi*lo, lo*hi
        const uint32_t aBase = (term == 2) ? saLo : saHi;
        const uint32_t bBase = (term == 1) ? sbLo : sbHi;
        #pragma unroll
        for (int ks = 0; ks < 8; ++ks) {
            uint32_t bf[8][2];
            #pragma unroll
            for (int nt = 0; nt < 8; ++nt)
                ldsm_x2(bf[nt], bBase + bOff + ks * 32 + nt * (8 * ROWB));
            #pragma unroll
            for (int ms = 0; ms < 2; ++ms) {
                uint32_t a[4];
                ldsm_x4(a, aBase + aOff + ms * (16 * ROWB) + ks * 32);
                #pragma unroll
                for (int nt = 0; nt < 8; ++nt)
                    mma_bf16(acc[ms][nt], a, bf[nt]);
            }
        }
    }

    // ---- Epilogue: add b1 (cols 0..63) and write to g_X -------------------
    const float* b1s = reinterpret_cast<const float*>(smem + SVEC);
    #pragma unroll
    for (int ms = 0; ms < 2; ++ms) {
        const int r0 = m0 + mW + ms * 16 + (lane >> 2);
        #pragma unroll
        for (int nt = 0; nt < 8; ++nt) {
            const int n = n0 + nt * 8 + (lane & 3) * 2;
            float ax = 0.f, ay = 0.f;
            if (nhalf == 0) { ax = b1s[n]; ay = b1s[n + 1]; }
            *reinterpret_cast<float2*>(&g_X[(size_t)r0 * 128 + n]) =
                make_float2(acc[ms][nt][0] + ax, acc[ms][nt][1] + ay);
            *reinterpret_cast<float2*>(&g_X[(size_t)(r0 + 8) * 128 + n]) =
                make_float2(acc[ms][nt][2] + ax, acc[ms][nt][3] + ay);
        }
    }
}

// ======================= Kernel 2: pairwise relu-dot =======================
#define K2_THREADS 256
#define K2_BT      4
#define XP2        132                                  // fp32 row pitch (words)
#define XT_BYTES   (K2_BT * F_SPARSE * XP2 * 4)         // 54912
#define SW2_OFF    XT_BYTES                             // W2: 64 f32
#define SLUT_OFF   (SW2_OFF + 256)
#define K2_SMEM    (SLUT_OFF + 328)                     // 55496

__global__ void __launch_bounds__(K2_THREADS, 4)
k2_pairs(const float* __restrict__ W2, const float* __restrict__ b2,
         float* __restrict__ out)
{
    extern __shared__ char smem[];
    float* sX = reinterpret_cast<float*>(smem);
    const int tid   = threadIdx.x;
    const int bbase = blockIdx.x * K2_BT;

    // ---- Load X tile: rows r = bl*26 + f, pitch 132, coalesced ------------
    for (int idx = tid; idx < K2_BT * F_SPARSE * 32; idx += K2_THREADS) {
        const int r = idx >> 5;
        const int c = idx & 31;
        const int bl = r / F_SPARSE;
        const int f  = r - bl * F_SPARSE;
        const float4 v = reinterpret_cast<const float4*>(
            &g_X[(size_t)(f * BATCH + bbase + bl) * 128])[c];
        *reinterpret_cast<float4*>(sX + r * XP2 + c * 4) = v;
    }
    if (tid < 64)
        reinterpret_cast<float*>(smem + SW2_OFF)[tid] = W2[tid];
    // pair -> i LUT
    if (tid < F_SPARSE - 1) {
        const int i = tid;
        const int pbase = i * (F_SPARSE - 1) - (i * (i - 1)) / 2;
        const int cnt   = F_SPARSE - 1 - i;
        for (int t = 0; t < cnt; ++t)
            smem[SLUT_OFF + pbase + t] = (char)i;
    }
    const float b2v = b2[0];
    __syncthreads();

    // ---- One output per thread-iteration ----------------------------------
    const float4* sW24 = reinterpret_cast<const float4*>(smem + SW2_OFF);

    for (int idx = tid; idx < K2_BT * NPAIR; idx += K2_THREADS) {
        const int bl = idx / NPAIR;
        const int p  = idx - bl * NPAIR;
        const int i  = (int)smem[SLUT_OFF + p];
        const int pbase = i * (F_SPARSE - 1) - (i * (i - 1)) / 2;
        const int j  = i + 1 + (p - pbase);

        const float4* Pa = reinterpret_cast<const float4*>(sX + (bl * F_SPARSE + i) * XP2);
        const float4* Pb = reinterpret_cast<const float4*>(sX + (bl * F_SPARSE + j) * XP2 + 64);

        float a0 = 0.f, a1 = 0.f;
        #pragma unroll
        for (int t = 0; t < 16; ++t) {
            const float4 x = Pa[t];
            const float4 y = Pb[t];
            const float4 w = sW24[t];
            a0 = fmaf(fmaxf(x.x + y.x, 0.f), w.x, a0);
            a1 = fmaf(fmaxf(x.y + y.y, 0.f), w.y, a1);
            a0 = fmaf(fmaxf(x.z + y.z, 0.f), w.z, a0);
            a1 = fmaf(fmaxf(x.w + y.w, 0.f), w.w, a1);
        }
        out[(size_t)(bbase + bl) * NPAIR + p] = a0 + a1 + b2v;
    }
}

// =========================== launcher ======================================
extern "C" void kernel_launch(void* const* d_in, const int* in_sizes, int n_in,
                              void* d_out, int out_size) {
    const float* emb = (const float*)d_in[0];
    const float* W1  = (const float*)d_in[1];
    const float* b1  = (const float*)d_in[2];
    const float* W2  = (const float*)d_in[3];
    const float* b2  = (const float*)d_in[4];
    float* out = (float*)d_out;
    (void)in_sizes; (void)n_in; (void)out_size;

    cudaFuncSetAttribute(k1_gemm,
                         cudaFuncAttributeMaxDynamicSharedMemorySize, K1_SMEM);
    cudaFuncSetAttribute(k2_pairs,
                         cudaFuncAttributeMaxDynamicSharedMemorySize, K2_SMEM);

    k1_gemm<<<M_TOTAL / K1_MT, K1_THREADS, K1_SMEM>>>(emb, W1, b1);
    k2_pairs<<<BATCH / K2_BT, K2_THREADS, K2_SMEM>>>(W2, b2, out);
}